// round 8
// baseline (speedup 1.0000x reference)
#include <cuda_runtime.h>
#include <cstdint>

#define NN 2048
#define KK 16
#define FF 256
#define OO 256
#define ROWS_MAX 4096
#define TILES_MAX 64

// ---------------- scratch (device globals; no allocation) ----------------
__device__ uint32_t g_mask[NN];
__device__ int      g_cnt[KK];
__device__ int      g_off[KK];
__device__ int      g_list[KK][NN];
__device__ int      g_tilek[TILES_MAX];
__device__ int      g_rownode[ROWS_MAX];
__device__ float    g_ak[(size_t)ROWS_MAX * NN];  // packed A_kk rows (pads zero-filled)
__device__ float    g_t[ROWS_MAX * FF];
__device__ float    g_y[ROWS_MAX * OO];
__device__ float    g_y2[ROWS_MAX * OO];          // split-K partial
__device__ float    g_h[NN * OO];
__device__ float    g_coarsen[KK * KK];
__device__ float    g_sum[OO];
__device__ float    g_sumsq[OO];
__device__ float    g_S[KK * OO];

// ---------------- kernel 1: partition + zero accumulators ----------------
__global__ __launch_bounds__(256) void k_partition(const float* __restrict__ x,
                                                   const float* __restrict__ wp,
                                                   const float* __restrict__ bp) {
    __shared__ float wsh[KK][FF];
    int tid = threadIdx.x;
    int b = blockIdx.x;

    for (int e = tid; e < FF * KK; e += 256) {
        int f = e / KK, k = e % KK;
        wsh[k][f] = wp[e];
    }
    #pragma unroll
    for (int q = 0; q < 8; q++)
        g_h[b * 2048 + q * 256 + tid] = 0.f;
    if (b == 0) {
        if (tid < KK * KK) g_coarsen[tid] = 0.f;
        g_sum[tid] = 0.f;
        g_sumsq[tid] = 0.f;
        #pragma unroll
        for (int e = 0; e < KK; e++) g_S[e * 256 + tid] = 0.f;
    }
    __syncthreads();

    int w = tid >> 5, lane = tid & 31;
    int i = b * 8 + w;

    float acc[KK];
    #pragma unroll
    for (int k = 0; k < KK; k++) acc[k] = 0.f;

    #pragma unroll
    for (int it = 0; it < 8; it++) {
        int f = it * 32 + lane;
        float xv = x[i * FF + f];
        #pragma unroll
        for (int k = 0; k < KK; k++) acc[k] += xv * wsh[k][f];
    }
    #pragma unroll
    for (int k = 0; k < KK; k++) {
        #pragma unroll
        for (int off = 16; off > 0; off >>= 1)
            acc[k] += __shfl_xor_sync(0xffffffffu, acc[k], off);
    }
    float mx = -1.f;
    #pragma unroll
    for (int k = 0; k < KK; k++) {
        float r = fmaxf(acc[k] + bp[k], 0.f);
        acc[k] = r;
        mx = fmaxf(mx, r);
    }
    uint32_t msk = 0;
    #pragma unroll
    for (int k = 0; k < KK; k++)
        if (acc[k] == mx) msk |= (1u << k);
    if (lane == 0) g_mask[i] = msk;
}

// ---------------- kernel 2: lists + offsets + tile map + rownode ----------------
__global__ __launch_bounds__(512) void k_lists() {
    int tid = threadIdx.x;
    int w = tid >> 5, lane = tid & 31;
    __shared__ int scnt[KK];
    __shared__ int soff[KK + 1];

    if (w < KK) {
        int cnt = 0;
        for (int base = 0; base < NN; base += 32) {
            uint32_t m = g_mask[base + lane];
            int pred = (m >> w) & 1u;
            unsigned bal = __ballot_sync(0xffffffffu, pred);
            if (pred) {
                int pos = cnt + __popc(bal & ((1u << lane) - 1u));
                g_list[w][pos] = base + lane;
            }
            cnt += __popc(bal);
        }
        if (lane == 0) { g_cnt[w] = cnt; scnt[w] = cnt; }
    }
    __syncthreads();

    if (tid == 0) {
        int o = 0;
        for (int k = 0; k < KK; k++) {
            soff[k] = o;
            g_off[k] = o;
            o += (scnt[k] + 63) & ~63;
        }
        soff[KK] = o;
        for (int t = 0; t < TILES_MAX; t++) g_tilek[t] = -1;
        for (int k = 0; k < KK; k++) {
            int t0 = soff[k] >> 6;
            int t1 = (soff[k] + ((scnt[k] + 63) & ~63)) >> 6;
            for (int t = t0; t < t1; t++) g_tilek[t] = k;
        }
    }
    __syncthreads();

    for (int r = tid; r < ROWS_MAX; r += 512) g_rownode[r] = -1;
    __syncthreads();
    for (int k = 0; k < KK; k++) {
        int off = soff[k], cnt = scnt[k];
        for (int p = tid; p < cnt; p += 512)
            g_rownode[off + p] = g_list[k][p];
    }
}

// ---------------- kernel 3: coarsen_adj = M adj M^T (R5-proven) ----------------
__global__ __launch_bounds__(256) void k_coarsen(const float* __restrict__ adj) {
    __shared__ uint32_t msh[NN];
    int tid = threadIdx.x;
    for (int e = tid; e < NN; e += 256) msh[e] = g_mask[e];
    __syncthreads();

    int w = tid >> 5, lane = tid & 31;
    int i = blockIdx.x * 8 + w;

    float acc[KK];
    #pragma unroll
    for (int k = 0; k < KK; k++) acc[k] = 0.f;
    const float4* row = reinterpret_cast<const float4*>(adj + (size_t)i * NN);
    #pragma unroll 2
    for (int jt = 0; jt < NN / 128; jt++) {
        int j4 = jt * 32 + lane;
        float4 v = row[j4];
        int j = j4 * 4;
        uint32_t m0 = msh[j], m1 = msh[j + 1], m2 = msh[j + 2], m3 = msh[j + 3];
        #pragma unroll
        for (int bb = 0; bb < KK; bb++) {
            float s = 0.f;
            if (m0 & (1u << bb)) s += v.x;
            if (m1 & (1u << bb)) s += v.y;
            if (m2 & (1u << bb)) s += v.z;
            if (m3 & (1u << bb)) s += v.w;
            acc[bb] += s;
        }
    }
    uint32_t mi = g_mask[i];
    #pragma unroll
    for (int bb = 0; bb < KK; bb++) {
        float val = acc[bb];
        #pragma unroll
        for (int off = 16; off > 0; off >>= 1)
            val += __shfl_xor_sync(0xffffffffu, val, off);
        if (lane == 0) {
            uint32_t ma = mi;
            while (ma) {
                int a = __ffs(ma) - 1;
                ma &= ma - 1;
                atomicAdd(&g_coarsen[a * KK + bb], val);
            }
        }
    }
}

// ---------------- kernel 4: gather packed A_kk rows (R5-proven, A only) ----------------
// grid (KK, 64), 256 threads.
__global__ __launch_bounds__(256) void k_gather(const float* __restrict__ adj) {
    int k = blockIdx.x;
    int by = blockIdx.y;
    int cnt = g_cnt[k];
    int off = g_off[k];
    int cp64 = (cnt + 63) & ~63;
    int c16 = (cnt + 15) & ~15;
    if (cp64 == 0) return;

    __shared__ int jl[NN];
    int tid = threadIdx.x;
    for (int j = tid; j < c16; j += 256) jl[j] = (j < cnt) ? g_list[k][j] : -1;
    __syncthreads();

    for (int pos = by; pos < cp64; pos += 64) {
        int gi = (pos < cnt) ? jl[pos] : -1;
        float4* dst = reinterpret_cast<float4*>(g_ak + (size_t)(off + pos) * NN);
        if (gi >= 0) {
            const float* src = adj + (size_t)gi * NN;
            for (int j4 = tid; j4 < (c16 >> 2); j4 += 256) {
                int j = j4 << 2;
                int ga = jl[j], gb = jl[j + 1], gc = jl[j + 2], gd = jl[j + 3];
                float4 v;
                v.x = (ga >= 0) ? src[ga] : 0.f;
                v.y = (gb >= 0) ? src[gb] : 0.f;
                v.z = (gc >= 0) ? src[gc] : 0.f;
                v.w = (gd >= 0) ? src[gd] : 0.f;
                dst[j4] = v;
            }
        } else {
            float4 z = make_float4(0.f, 0.f, 0.f, 0.f);
            for (int j4 = tid; j4 < (c16 >> 2); j4 += 256) dst[j4] = z;
        }
    }
}

// ---------------- kernel 5: t = A_kk @ X_k + 2 X_k (x read directly) ----------------
// grid (TILES_MAX, 4), 256 threads. 64x64 tile, 4x4/thread, kb=32, reg prefetch.
__global__ __launch_bounds__(256) void k_agg(const float* __restrict__ x) {
    int tile = blockIdx.x, ct = blockIdx.y;
    int k = g_tilek[tile];
    if (k < 0) return;
    int cnt = g_cnt[k];
    int c32 = (cnt + 31) & ~31;
    int row0 = tile * 64;
    int offk = g_off[k];

    __shared__ float a_sh[32][65];   // [kk][r]
    __shared__ float x_sh[32][68];   // [kk][c]

    int tid = threadIdx.x;
    int tx = tid & 15, ty = tid >> 4;
    int ar = tid >> 2, aq = (tid & 3) << 2;
    int xf = tid >> 4, xc = (tid & 15) << 2;
    int cb = ct * 64;

    const float* abase = g_ak + (size_t)(row0 + ar) * NN;

    float4 pa0, pa1, px0, px1;
    {
        pa0 = *reinterpret_cast<const float4*>(abase + aq);
        pa1 = *reinterpret_cast<const float4*>(abase + 16 + aq);
        int r0i = g_rownode[offk + xf];
        int r1i = g_rownode[offk + 16 + xf];
        px0 = (r0i >= 0) ? *reinterpret_cast<const float4*>(x + (size_t)r0i * FF + cb + xc)
                         : make_float4(0.f, 0.f, 0.f, 0.f);
        px1 = (r1i >= 0) ? *reinterpret_cast<const float4*>(x + (size_t)r1i * FF + cb + xc)
                         : make_float4(0.f, 0.f, 0.f, 0.f);
    }

    float acc[4][4];
    #pragma unroll
    for (int i = 0; i < 4; i++)
        #pragma unroll
        for (int j = 0; j < 4; j++) acc[i][j] = 0.f;

    for (int kb = 0; kb < c32; kb += 32) {
        a_sh[aq + 0][ar] = pa0.x; a_sh[aq + 1][ar] = pa0.y;
        a_sh[aq + 2][ar] = pa0.z; a_sh[aq + 3][ar] = pa0.w;
        a_sh[aq + 16][ar] = pa1.x; a_sh[aq + 17][ar] = pa1.y;
        a_sh[aq + 18][ar] = pa1.z; a_sh[aq + 19][ar] = pa1.w;
        *reinterpret_cast<float4*>(&x_sh[xf][xc]) = px0;
        *reinterpret_cast<float4*>(&x_sh[xf + 16][xc]) = px1;
        __syncthreads();
        int kn = kb + 32;
        if (kn < c32) {
            pa0 = *reinterpret_cast<const float4*>(abase + kn + aq);
            pa1 = *reinterpret_cast<const float4*>(abase + kn + 16 + aq);
            int r0i = g_rownode[offk + kn + xf];
            int r1i = g_rownode[offk + kn + 16 + xf];
            px0 = (r0i >= 0) ? *reinterpret_cast<const float4*>(x + (size_t)r0i * FF + cb + xc)
                             : make_float4(0.f, 0.f, 0.f, 0.f);
            px1 = (r1i >= 0) ? *reinterpret_cast<const float4*>(x + (size_t)r1i * FF + cb + xc)
                             : make_float4(0.f, 0.f, 0.f, 0.f);
        }
        #pragma unroll
        for (int kk = 0; kk < 32; kk++) {
            float a0 = a_sh[kk][ty * 4 + 0];
            float a1 = a_sh[kk][ty * 4 + 1];
            float a2 = a_sh[kk][ty * 4 + 2];
            float a3 = a_sh[kk][ty * 4 + 3];
            float4 wv = *reinterpret_cast<const float4*>(&x_sh[kk][tx * 4]);
            acc[0][0] += a0 * wv.x; acc[0][1] += a0 * wv.y; acc[0][2] += a0 * wv.z; acc[0][3] += a0 * wv.w;
            acc[1][0] += a1 * wv.x; acc[1][1] += a1 * wv.y; acc[1][2] += a1 * wv.z; acc[1][3] += a1 * wv.w;
            acc[2][0] += a2 * wv.x; acc[2][1] += a2 * wv.y; acc[2][2] += a2 * wv.z; acc[2][3] += a2 * wv.w;
            acc[3][0] += a3 * wv.x; acc[3][1] += a3 * wv.y; acc[3][2] += a3 * wv.z; acc[3][3] += a3 * wv.w;
        }
        __syncthreads();
    }

    #pragma unroll
    for (int i = 0; i < 4; i++) {
        int row = row0 + ty * 4 + i;
        int gi = g_rownode[row];
        float4 xv = (gi >= 0) ? *reinterpret_cast<const float4*>(x + (size_t)gi * FF + cb + tx * 4)
                              : make_float4(0.f, 0.f, 0.f, 0.f);
        float4 o = make_float4(acc[i][0] + 2.f * xv.x, acc[i][1] + 2.f * xv.y,
                               acc[i][2] + 2.f * xv.z, acc[i][3] + 2.f * xv.w);
        *reinterpret_cast<float4*>(g_t + (size_t)row * FF + cb + tx * 4) = o;
    }
}

// ---------------- kernel 6: y = t @ W_k (split-K = 2) ----------------
__global__ __launch_bounds__(256) void k_wgemm(const float* __restrict__ W) {
    int tile = blockIdx.x, ct = blockIdx.y, z = blockIdx.z;
    int k = g_tilek[tile];
    if (k < 0) return;
    int row0 = tile * 64;
    const float* Wk = W + (size_t)k * FF * OO;
    int kbase = z * 128;

    __shared__ float t_sh[32][65];
    __shared__ float w_sh[32][68];

    int tid = threadIdx.x;
    int tx = tid & 15, ty = tid >> 4;
    int ar = tid >> 2, aq = (tid & 3) << 2;
    int wf = tid >> 4, wc = (tid & 15) << 2;

    const float* tbase = g_t + (size_t)(row0 + ar) * FF + kbase;
    float4 pt0, pt1, pw0, pw1;
    pt0 = *reinterpret_cast<const float4*>(tbase + aq);
    pt1 = *reinterpret_cast<const float4*>(tbase + 16 + aq);
    pw0 = *reinterpret_cast<const float4*>(Wk + (size_t)(kbase + wf) * OO + ct * 64 + wc);
    pw1 = *reinterpret_cast<const float4*>(Wk + (size_t)(kbase + 16 + wf) * OO + ct * 64 + wc);

    float acc[4][4];
    #pragma unroll
    for (int i = 0; i < 4; i++)
        #pragma unroll
        for (int j = 0; j < 4; j++) acc[i][j] = 0.f;

    #pragma unroll 1
    for (int kb = 0; kb < 128; kb += 32) {
        t_sh[aq + 0][ar] = pt0.x; t_sh[aq + 1][ar] = pt0.y;
        t_sh[aq + 2][ar] = pt0.z; t_sh[aq + 3][ar] = pt0.w;
        t_sh[aq + 16][ar] = pt1.x; t_sh[aq + 17][ar] = pt1.y;
        t_sh[aq + 18][ar] = pt1.z; t_sh[aq + 19][ar] = pt1.w;
        *reinterpret_cast<float4*>(&w_sh[wf][wc]) = pw0;
        *reinterpret_cast<float4*>(&w_sh[wf + 16][wc]) = pw1;
        __syncthreads();
        int kn = kb + 32;
        if (kn < 128) {
            pt0 = *reinterpret_cast<const float4*>(tbase + kn + aq);
            pt1 = *reinterpret_cast<const float4*>(tbase + kn + 16 + aq);
            pw0 = *reinterpret_cast<const float4*>(Wk + (size_t)(kbase + kn + wf) * OO + ct * 64 + wc);
            pw1 = *reinterpret_cast<const float4*>(Wk + (size_t)(kbase + kn + 16 + wf) * OO + ct * 64 + wc);
        }
        #pragma unroll
        for (int kk = 0; kk < 32; kk++) {
            float a0 = t_sh[kk][ty * 4 + 0];
            float a1 = t_sh[kk][ty * 4 + 1];
            float a2 = t_sh[kk][ty * 4 + 2];
            float a3 = t_sh[kk][ty * 4 + 3];
            float4 wv = *reinterpret_cast<const float4*>(&w_sh[kk][tx * 4]);
            acc[0][0] += a0 * wv.x; acc[0][1] += a0 * wv.y; acc[0][2] += a0 * wv.z; acc[0][3] += a0 * wv.w;
            acc[1][0] += a1 * wv.x; acc[1][1] += a1 * wv.y; acc[1][2] += a1 * wv.z; acc[1][3] += a1 * wv.w;
            acc[2][0] += a2 * wv.x; acc[2][1] += a2 * wv.y; acc[2][2] += a2 * wv.z; acc[2][3] += a2 * wv.w;
            acc[3][0] += a3 * wv.x; acc[3][1] += a3 * wv.y; acc[3][2] += a3 * wv.z; acc[3][3] += a3 * wv.w;
        }
        __syncthreads();
    }

    float* yb = z ? g_y2 : g_y;
    #pragma unroll
    for (int i = 0; i < 4; i++) {
        int row = row0 + ty * 4 + i;
        *reinterpret_cast<float4*>(yb + (size_t)row * OO + ct * 64 + tx * 4) =
            make_float4(acc[i][0], acc[i][1], acc[i][2], acc[i][3]);
    }
}

// ---------------- kernel 7: L2 normalize rows + scatter into g_h ----------------
__global__ __launch_bounds__(256) void k_norm() {
    int w = threadIdx.x >> 5, lane = threadIdx.x & 31;
    int r = blockIdx.x * 8 + w;
    int gi = g_rownode[r];
    if (gi < 0) return;

    const float4* yr  = reinterpret_cast<const float4*>(g_y  + (size_t)r * OO);
    const float4* yr2 = reinterpret_cast<const float4*>(g_y2 + (size_t)r * OO);
    float4 a = yr[lane * 2], b = yr[lane * 2 + 1];
    float4 a2 = yr2[lane * 2], b2 = yr2[lane * 2 + 1];
    a.x += a2.x; a.y += a2.y; a.z += a2.z; a.w += a2.w;
    b.x += b2.x; b.y += b2.y; b.z += b2.z; b.w += b2.w;
    float ss = a.x * a.x + a.y * a.y + a.z * a.z + a.w * a.w
             + b.x * b.x + b.y * b.y + b.z * b.z + b.w * b.w;
    #pragma unroll
    for (int off = 16; off > 0; off >>= 1)
        ss += __shfl_xor_sync(0xffffffffu, ss, off);
    float rn = 1.f / fmaxf(sqrtf(ss), 1e-12f);

    float* hb = g_h + (size_t)gi * OO + lane * 8;
    atomicAdd(hb + 0, a.x * rn); atomicAdd(hb + 1, a.y * rn);
    atomicAdd(hb + 2, a.z * rn); atomicAdd(hb + 3, a.w * rn);
    atomicAdd(hb + 4, b.x * rn); atomicAdd(hb + 5, b.y * rn);
    atomicAdd(hb + 6, b.z * rn); atomicAdd(hb + 7, b.w * rn);
}

// ---------------- kernel 8: fused BN stats + per-cluster column sums ----------------
// 32 blocks x 64 rows. Thread o owns column o; per-cluster partials in smem (column-private).
__global__ __launch_bounds__(256) void k_statsum() {
    __shared__ float sS[KK][OO];
    int o = threadIdx.x;
    #pragma unroll
    for (int b = 0; b < KK; b++) sS[b][o] = 0.f;

    int rb = blockIdx.x * 64;
    float s = 0.f, ss = 0.f;
    #pragma unroll 4
    for (int r = 0; r < 64; r++) {
        int rowi = rb + r;
        float v = fmaxf(g_h[(size_t)rowi * OO + o], 0.f);
        s += v;
        ss += v * v;
        uint32_t m = g_mask[rowi];
        while (m) {
            int b = __ffs(m) - 1;
            m &= m - 1;
            sS[b][o] += v;
        }
    }
    atomicAdd(&g_sum[o], s);
    atomicAdd(&g_sumsq[o], ss);
    #pragma unroll
    for (int b = 0; b < KK; b++) {
        float val = sS[b][o];
        if (val != 0.f) atomicAdd(&g_S[b * OO + o], val);
    }
}

// ---------------- kernel 9: final output ----------------
__global__ __launch_bounds__(256) void k_final(float* __restrict__ out) {
    int k = blockIdx.x, o = threadIdx.x;
    float mean = g_sum[o] * (1.f / NN);
    float var = g_sumsq[o] * (1.f / NN) - mean * mean;
    float rstd = rsqrtf(var + 1e-5f);
    out[k * OO + o] = (g_S[k * OO + o] - (float)g_cnt[k] * mean) * rstd;
    if (o < KK) out[KK * OO + k * KK + o] = g_coarsen[k * KK + o];
}

// ---------------- launch ----------------
extern "C" void kernel_launch(void* const* d_in, const int* in_sizes, int n_in,
                              void* d_out, int out_size) {
    const float* x   = (const float*)d_in[0];
    const float* adj = (const float*)d_in[1];
    const float* wp  = (const float*)d_in[2];
    const float* bp  = (const float*)d_in[3];
    const float* W   = (const float*)d_in[4];
    float* out = (float*)d_out;

    k_partition<<<256, 256>>>(x, wp, bp);
    k_lists<<<1, 512>>>();
    k_coarsen<<<256, 256>>>(adj);
    k_gather<<<dim3(KK, 64), 256>>>(adj);
    k_agg<<<dim3(TILES_MAX, 4), 256>>>(x);
    k_wgemm<<<dim3(TILES_MAX, 4, 2), 256>>>(W);
    k_norm<<<ROWS_MAX / 8, 256>>>();
    k_statsum<<<32, 256>>>();
    k_final<<<KK, 256>>>(out);
}

// round 9
// speedup vs baseline: 1.3337x; 1.3337x over previous
#include <cuda_runtime.h>
#include <cstdint>

#define NN 2048
#define KK 16
#define FF 256
#define OO 256
#define ROWS_MAX 4096
#define TILES_MAX 64

// ---------------- scratch (device globals; no allocation) ----------------
__device__ uint32_t g_mask[NN];
__device__ int      g_cnt[KK];
__device__ int      g_off[KK];
__device__ int      g_list[KK][NN];
__device__ int      g_tilek[TILES_MAX];
__device__ int      g_rownode[ROWS_MAX];
__device__ float    g_ak[(size_t)ROWS_MAX * NN];  // packed A_kk rows (pads zero-filled)
__device__ float    g_t[ROWS_MAX * FF];
__device__ float    g_y[ROWS_MAX * OO];
__device__ float    g_y2[ROWS_MAX * OO];          // split-K partial
__device__ float    g_h[NN * OO];
__device__ float    g_coarsen[KK * KK];
__device__ float    g_sum[OO];
__device__ float    g_sumsq[OO];
__device__ float    g_S[KK * OO];

// ---------------- kernel 1: partition + zero accumulators ----------------
__global__ __launch_bounds__(256) void k_partition(const float* __restrict__ x,
                                                   const float* __restrict__ wp,
                                                   const float* __restrict__ bp) {
    __shared__ float wsh[KK][FF];
    int tid = threadIdx.x;
    int b = blockIdx.x;

    for (int e = tid; e < FF * KK; e += 256) {
        int f = e / KK, k = e % KK;
        wsh[k][f] = wp[e];
    }
    #pragma unroll
    for (int q = 0; q < 8; q++)
        g_h[b * 2048 + q * 256 + tid] = 0.f;
    if (b == 0) {
        if (tid < KK * KK) g_coarsen[tid] = 0.f;
        g_sum[tid] = 0.f;
        g_sumsq[tid] = 0.f;
        #pragma unroll
        for (int e = 0; e < KK; e++) g_S[e * 256 + tid] = 0.f;
    }
    __syncthreads();

    int w = tid >> 5, lane = tid & 31;
    int i = b * 8 + w;

    float acc[KK];
    #pragma unroll
    for (int k = 0; k < KK; k++) acc[k] = 0.f;

    #pragma unroll
    for (int it = 0; it < 8; it++) {
        int f = it * 32 + lane;
        float xv = x[i * FF + f];
        #pragma unroll
        for (int k = 0; k < KK; k++) acc[k] += xv * wsh[k][f];
    }
    #pragma unroll
    for (int k = 0; k < KK; k++) {
        #pragma unroll
        for (int off = 16; off > 0; off >>= 1)
            acc[k] += __shfl_xor_sync(0xffffffffu, acc[k], off);
    }
    float mx = -1.f;
    #pragma unroll
    for (int k = 0; k < KK; k++) {
        float r = fmaxf(acc[k] + bp[k], 0.f);
        acc[k] = r;
        mx = fmaxf(mx, r);
    }
    uint32_t msk = 0;
    #pragma unroll
    for (int k = 0; k < KK; k++)
        if (acc[k] == mx) msk |= (1u << k);
    if (lane == 0) g_mask[i] = msk;
}

// ---------------- kernel 2: lists + offsets + tile map + rownode ----------------
__global__ __launch_bounds__(512) void k_lists() {
    int tid = threadIdx.x;
    int w = tid >> 5, lane = tid & 31;
    __shared__ int scnt[KK];
    __shared__ int soff[KK + 1];

    if (w < KK) {
        int cnt = 0;
        for (int base = 0; base < NN; base += 32) {
            uint32_t m = g_mask[base + lane];
            int pred = (m >> w) & 1u;
            unsigned bal = __ballot_sync(0xffffffffu, pred);
            if (pred) {
                int pos = cnt + __popc(bal & ((1u << lane) - 1u));
                g_list[w][pos] = base + lane;
            }
            cnt += __popc(bal);
        }
        if (lane == 0) { g_cnt[w] = cnt; scnt[w] = cnt; }
    }
    __syncthreads();

    if (tid == 0) {
        int o = 0;
        for (int k = 0; k < KK; k++) {
            soff[k] = o;
            g_off[k] = o;
            o += (scnt[k] + 63) & ~63;
        }
        soff[KK] = o;
        for (int t = 0; t < TILES_MAX; t++) g_tilek[t] = -1;
        for (int k = 0; k < KK; k++) {
            int t0 = soff[k] >> 6;
            int t1 = (soff[k] + ((scnt[k] + 63) & ~63)) >> 6;
            for (int t = t0; t < t1; t++) g_tilek[t] = k;
        }
    }
    __syncthreads();

    for (int r = tid; r < ROWS_MAX; r += 512) g_rownode[r] = -1;
    __syncthreads();
    for (int k = 0; k < KK; k++) {
        int off = soff[k], cnt = scnt[k];
        for (int p = tid; p < cnt; p += 512)
            g_rownode[off + p] = g_list[k][p];
    }
}

// ---------------- kernel 3: coarsen_adj = M adj M^T (runs on side stream) ----------------
__global__ __launch_bounds__(256) void k_coarsen(const float* __restrict__ adj) {
    __shared__ uint32_t msh[NN];
    int tid = threadIdx.x;
    for (int e = tid; e < NN; e += 256) msh[e] = g_mask[e];
    __syncthreads();

    int w = tid >> 5, lane = tid & 31;
    int i = blockIdx.x * 8 + w;

    float acc[KK];
    #pragma unroll
    for (int k = 0; k < KK; k++) acc[k] = 0.f;
    const float4* row = reinterpret_cast<const float4*>(adj + (size_t)i * NN);
    #pragma unroll 2
    for (int jt = 0; jt < NN / 128; jt++) {
        int j4 = jt * 32 + lane;
        float4 v = row[j4];
        int j = j4 * 4;
        uint32_t m0 = msh[j], m1 = msh[j + 1], m2 = msh[j + 2], m3 = msh[j + 3];
        #pragma unroll
        for (int bb = 0; bb < KK; bb++) {
            float s = 0.f;
            if (m0 & (1u << bb)) s += v.x;
            if (m1 & (1u << bb)) s += v.y;
            if (m2 & (1u << bb)) s += v.z;
            if (m3 & (1u << bb)) s += v.w;
            acc[bb] += s;
        }
    }
    uint32_t mi = g_mask[i];
    #pragma unroll
    for (int bb = 0; bb < KK; bb++) {
        float val = acc[bb];
        #pragma unroll
        for (int off = 16; off > 0; off >>= 1)
            val += __shfl_xor_sync(0xffffffffu, val, off);
        if (lane == 0) {
            uint32_t ma = mi;
            while (ma) {
                int a = __ffs(ma) - 1;
                ma &= ma - 1;
                atomicAdd(&g_coarsen[a * KK + bb], val);
            }
        }
    }
}

// ---------------- kernel 4: gather packed A_kk rows ----------------
// grid (KK, 128), 256 threads.
__global__ __launch_bounds__(256) void k_gather(const float* __restrict__ adj) {
    int k = blockIdx.x;
    int by = blockIdx.y;
    int cnt = g_cnt[k];
    int off = g_off[k];
    int cp64 = (cnt + 63) & ~63;
    int c16 = (cnt + 15) & ~15;
    if (cp64 == 0 || by >= cp64) return;

    __shared__ int jl[NN];
    int tid = threadIdx.x;
    for (int j = tid; j < c16; j += 256) jl[j] = (j < cnt) ? g_list[k][j] : -1;
    __syncthreads();

    for (int pos = by; pos < cp64; pos += 128) {
        int gi = (pos < cnt) ? jl[pos] : -1;
        float4* dst = reinterpret_cast<float4*>(g_ak + (size_t)(off + pos) * NN);
        if (gi >= 0) {
            const float* src = adj + (size_t)gi * NN;
            for (int j4 = tid; j4 < (c16 >> 2); j4 += 256) {
                int j = j4 << 2;
                int ga = jl[j], gb = jl[j + 1], gc = jl[j + 2], gd = jl[j + 3];
                float4 v;
                v.x = (ga >= 0) ? src[ga] : 0.f;
                v.y = (gb >= 0) ? src[gb] : 0.f;
                v.z = (gc >= 0) ? src[gc] : 0.f;
                v.w = (gd >= 0) ? src[gd] : 0.f;
                dst[j4] = v;
            }
        } else {
            float4 z = make_float4(0.f, 0.f, 0.f, 0.f);
            for (int j4 = tid; j4 < (c16 >> 2); j4 += 256) dst[j4] = z;
        }
    }
}

// ---------------- kernel 5: t = A_kk @ X_k + 2 X_k (x read directly) ----------------
__global__ __launch_bounds__(256) void k_agg(const float* __restrict__ x) {
    int tile = blockIdx.x, ct = blockIdx.y;
    int k = g_tilek[tile];
    if (k < 0) return;
    int cnt = g_cnt[k];
    int c32 = (cnt + 31) & ~31;
    int row0 = tile * 64;
    int offk = g_off[k];

    __shared__ float a_sh[32][65];   // [kk][r]
    __shared__ float x_sh[32][68];   // [kk][c]

    int tid = threadIdx.x;
    int tx = tid & 15, ty = tid >> 4;
    int ar = tid >> 2, aq = (tid & 3) << 2;
    int xf = tid >> 4, xc = (tid & 15) << 2;
    int cb = ct * 64;

    const float* abase = g_ak + (size_t)(row0 + ar) * NN;

    float4 pa0, pa1, px0, px1;
    {
        pa0 = *reinterpret_cast<const float4*>(abase + aq);
        pa1 = *reinterpret_cast<const float4*>(abase + 16 + aq);
        int r0i = g_rownode[offk + xf];
        int r1i = g_rownode[offk + 16 + xf];
        px0 = (r0i >= 0) ? *reinterpret_cast<const float4*>(x + (size_t)r0i * FF + cb + xc)
                         : make_float4(0.f, 0.f, 0.f, 0.f);
        px1 = (r1i >= 0) ? *reinterpret_cast<const float4*>(x + (size_t)r1i * FF + cb + xc)
                         : make_float4(0.f, 0.f, 0.f, 0.f);
    }

    float acc[4][4];
    #pragma unroll
    for (int i = 0; i < 4; i++)
        #pragma unroll
        for (int j = 0; j < 4; j++) acc[i][j] = 0.f;

    for (int kb = 0; kb < c32; kb += 32) {
        a_sh[aq + 0][ar] = pa0.x; a_sh[aq + 1][ar] = pa0.y;
        a_sh[aq + 2][ar] = pa0.z; a_sh[aq + 3][ar] = pa0.w;
        a_sh[aq + 16][ar] = pa1.x; a_sh[aq + 17][ar] = pa1.y;
        a_sh[aq + 18][ar] = pa1.z; a_sh[aq + 19][ar] = pa1.w;
        *reinterpret_cast<float4*>(&x_sh[xf][xc]) = px0;
        *reinterpret_cast<float4*>(&x_sh[xf + 16][xc]) = px1;
        __syncthreads();
        int kn = kb + 32;
        if (kn < c32) {
            pa0 = *reinterpret_cast<const float4*>(abase + kn + aq);
            pa1 = *reinterpret_cast<const float4*>(abase + kn + 16 + aq);
            int r0i = g_rownode[offk + kn + xf];
            int r1i = g_rownode[offk + kn + 16 + xf];
            px0 = (r0i >= 0) ? *reinterpret_cast<const float4*>(x + (size_t)r0i * FF + cb + xc)
                             : make_float4(0.f, 0.f, 0.f, 0.f);
            px1 = (r1i >= 0) ? *reinterpret_cast<const float4*>(x + (size_t)r1i * FF + cb + xc)
                             : make_float4(0.f, 0.f, 0.f, 0.f);
        }
        #pragma unroll
        for (int kk = 0; kk < 32; kk++) {
            float a0 = a_sh[kk][ty * 4 + 0];
            float a1 = a_sh[kk][ty * 4 + 1];
            float a2 = a_sh[kk][ty * 4 + 2];
            float a3 = a_sh[kk][ty * 4 + 3];
            float4 wv = *reinterpret_cast<const float4*>(&x_sh[kk][tx * 4]);
            acc[0][0] += a0 * wv.x; acc[0][1] += a0 * wv.y; acc[0][2] += a0 * wv.z; acc[0][3] += a0 * wv.w;
            acc[1][0] += a1 * wv.x; acc[1][1] += a1 * wv.y; acc[1][2] += a1 * wv.z; acc[1][3] += a1 * wv.w;
            acc[2][0] += a2 * wv.x; acc[2][1] += a2 * wv.y; acc[2][2] += a2 * wv.z; acc[2][3] += a2 * wv.w;
            acc[3][0] += a3 * wv.x; acc[3][1] += a3 * wv.y; acc[3][2] += a3 * wv.z; acc[3][3] += a3 * wv.w;
        }
        __syncthreads();
    }

    #pragma unroll
    for (int i = 0; i < 4; i++) {
        int row = row0 + ty * 4 + i;
        int gi = g_rownode[row];
        float4 xv = (gi >= 0) ? *reinterpret_cast<const float4*>(x + (size_t)gi * FF + cb + tx * 4)
                              : make_float4(0.f, 0.f, 0.f, 0.f);
        float4 o = make_float4(acc[i][0] + 2.f * xv.x, acc[i][1] + 2.f * xv.y,
                               acc[i][2] + 2.f * xv.z, acc[i][3] + 2.f * xv.w);
        *reinterpret_cast<float4*>(g_t + (size_t)row * FF + cb + tx * 4) = o;
    }
}

// ---------------- kernel 6: y = t @ W_k (split-K = 2) ----------------
__global__ __launch_bounds__(256) void k_wgemm(const float* __restrict__ W) {
    int tile = blockIdx.x, ct = blockIdx.y, z = blockIdx.z;
    int k = g_tilek[tile];
    if (k < 0) return;
    int row0 = tile * 64;
    const float* Wk = W + (size_t)k * FF * OO;
    int kbase = z * 128;

    __shared__ float t_sh[32][65];
    __shared__ float w_sh[32][68];

    int tid = threadIdx.x;
    int tx = tid & 15, ty = tid >> 4;
    int ar = tid >> 2, aq = (tid & 3) << 2;
    int wf = tid >> 4, wc = (tid & 15) << 2;

    const float* tbase = g_t + (size_t)(row0 + ar) * FF + kbase;
    float4 pt0, pt1, pw0, pw1;
    pt0 = *reinterpret_cast<const float4*>(tbase + aq);
    pt1 = *reinterpret_cast<const float4*>(tbase + 16 + aq);
    pw0 = *reinterpret_cast<const float4*>(Wk + (size_t)(kbase + wf) * OO + ct * 64 + wc);
    pw1 = *reinterpret_cast<const float4*>(Wk + (size_t)(kbase + 16 + wf) * OO + ct * 64 + wc);

    float acc[4][4];
    #pragma unroll
    for (int i = 0; i < 4; i++)
        #pragma unroll
        for (int j = 0; j < 4; j++) acc[i][j] = 0.f;

    #pragma unroll 1
    for (int kb = 0; kb < 128; kb += 32) {
        t_sh[aq + 0][ar] = pt0.x; t_sh[aq + 1][ar] = pt0.y;
        t_sh[aq + 2][ar] = pt0.z; t_sh[aq + 3][ar] = pt0.w;
        t_sh[aq + 16][ar] = pt1.x; t_sh[aq + 17][ar] = pt1.y;
        t_sh[aq + 18][ar] = pt1.z; t_sh[aq + 19][ar] = pt1.w;
        *reinterpret_cast<float4*>(&w_sh[wf][wc]) = pw0;
        *reinterpret_cast<float4*>(&w_sh[wf + 16][wc]) = pw1;
        __syncthreads();
        int kn = kb + 32;
        if (kn < 128) {
            pt0 = *reinterpret_cast<const float4*>(tbase + kn + aq);
            pt1 = *reinterpret_cast<const float4*>(tbase + kn + 16 + aq);
            pw0 = *reinterpret_cast<const float4*>(Wk + (size_t)(kbase + kn + wf) * OO + ct * 64 + wc);
            pw1 = *reinterpret_cast<const float4*>(Wk + (size_t)(kbase + kn + 16 + wf) * OO + ct * 64 + wc);
        }
        #pragma unroll
        for (int kk = 0; kk < 32; kk++) {
            float a0 = t_sh[kk][ty * 4 + 0];
            float a1 = t_sh[kk][ty * 4 + 1];
            float a2 = t_sh[kk][ty * 4 + 2];
            float a3 = t_sh[kk][ty * 4 + 3];
            float4 wv = *reinterpret_cast<const float4*>(&w_sh[kk][tx * 4]);
            acc[0][0] += a0 * wv.x; acc[0][1] += a0 * wv.y; acc[0][2] += a0 * wv.z; acc[0][3] += a0 * wv.w;
            acc[1][0] += a1 * wv.x; acc[1][1] += a1 * wv.y; acc[1][2] += a1 * wv.z; acc[1][3] += a1 * wv.w;
            acc[2][0] += a2 * wv.x; acc[2][1] += a2 * wv.y; acc[2][2] += a2 * wv.z; acc[2][3] += a2 * wv.w;
            acc[3][0] += a3 * wv.x; acc[3][1] += a3 * wv.y; acc[3][2] += a3 * wv.z; acc[3][3] += a3 * wv.w;
        }
        __syncthreads();
    }

    float* yb = z ? g_y2 : g_y;
    #pragma unroll
    for (int i = 0; i < 4; i++) {
        int row = row0 + ty * 4 + i;
        *reinterpret_cast<float4*>(yb + (size_t)row * OO + ct * 64 + tx * 4) =
            make_float4(acc[i][0], acc[i][1], acc[i][2], acc[i][3]);
    }
}

// ---------------- kernel 7: L2 normalize rows + scatter into g_h ----------------
__global__ __launch_bounds__(256) void k_norm() {
    int w = threadIdx.x >> 5, lane = threadIdx.x & 31;
    int r = blockIdx.x * 8 + w;
    int gi = g_rownode[r];
    if (gi < 0) return;

    const float4* yr  = reinterpret_cast<const float4*>(g_y  + (size_t)r * OO);
    const float4* yr2 = reinterpret_cast<const float4*>(g_y2 + (size_t)r * OO);
    float4 a = yr[lane * 2], b = yr[lane * 2 + 1];
    float4 a2 = yr2[lane * 2], b2 = yr2[lane * 2 + 1];
    a.x += a2.x; a.y += a2.y; a.z += a2.z; a.w += a2.w;
    b.x += b2.x; b.y += b2.y; b.z += b2.z; b.w += b2.w;
    float ss = a.x * a.x + a.y * a.y + a.z * a.z + a.w * a.w
             + b.x * b.x + b.y * b.y + b.z * b.z + b.w * b.w;
    #pragma unroll
    for (int off = 16; off > 0; off >>= 1)
        ss += __shfl_xor_sync(0xffffffffu, ss, off);
    float rn = 1.f / fmaxf(sqrtf(ss), 1e-12f);

    float* hb = g_h + (size_t)gi * OO + lane * 8;
    atomicAdd(hb + 0, a.x * rn); atomicAdd(hb + 1, a.y * rn);
    atomicAdd(hb + 2, a.z * rn); atomicAdd(hb + 3, a.w * rn);
    atomicAdd(hb + 4, b.x * rn); atomicAdd(hb + 5, b.y * rn);
    atomicAdd(hb + 6, b.z * rn); atomicAdd(hb + 7, b.w * rn);
}

// ---------------- kernel 8: fused BN stats + per-cluster column sums ----------------
__global__ __launch_bounds__(256) void k_statsum() {
    __shared__ float sS[KK][OO];
    int o = threadIdx.x;
    #pragma unroll
    for (int b = 0; b < KK; b++) sS[b][o] = 0.f;

    int rb = blockIdx.x * 64;
    float s = 0.f, ss = 0.f;
    #pragma unroll 4
    for (int r = 0; r < 64; r++) {
        int rowi = rb + r;
        float v = fmaxf(g_h[(size_t)rowi * OO + o], 0.f);
        s += v;
        ss += v * v;
        uint32_t m = g_mask[rowi];
        while (m) {
            int b = __ffs(m) - 1;
            m &= m - 1;
            sS[b][o] += v;
        }
    }
    atomicAdd(&g_sum[o], s);
    atomicAdd(&g_sumsq[o], ss);
    #pragma unroll
    for (int b = 0; b < KK; b++) {
        float val = sS[b][o];
        if (val != 0.f) atomicAdd(&g_S[b * OO + o], val);
    }
}

// ---------------- kernel 9: final output ----------------
__global__ __launch_bounds__(256) void k_final(float* __restrict__ out) {
    int k = blockIdx.x, o = threadIdx.x;
    float mean = g_sum[o] * (1.f / NN);
    float var = g_sumsq[o] * (1.f / NN) - mean * mean;
    float rstd = rsqrtf(var + 1e-5f);
    out[k * OO + o] = (g_S[k * OO + o] - (float)g_cnt[k] * mean) * rstd;
    if (o < KK) out[KK * OO + k * KK + o] = g_coarsen[k * KK + o];
}

// ---------------- launch: fork-join, coarsen on side stream ----------------
extern "C" void kernel_launch(void* const* d_in, const int* in_sizes, int n_in,
                              void* d_out, int out_size) {
    const float* x   = (const float*)d_in[0];
    const float* adj = (const float*)d_in[1];
    const float* wp  = (const float*)d_in[2];
    const float* bp  = (const float*)d_in[3];
    const float* W   = (const float*)d_in[4];
    float* out = (float*)d_out;

    static cudaStream_t s2 = nullptr;
    static cudaEvent_t ev_fork = nullptr, ev_join = nullptr;
    if (s2 == nullptr) {
        cudaStreamCreateWithFlags(&s2, cudaStreamNonBlocking);
        cudaEventCreateWithFlags(&ev_fork, cudaEventDisableTiming);
        cudaEventCreateWithFlags(&ev_join, cudaEventDisableTiming);
    }

    k_partition<<<256, 256>>>(x, wp, bp);

    // fork: coarsen depends only on g_mask
    cudaEventRecord(ev_fork, 0);
    cudaStreamWaitEvent(s2, ev_fork, 0);
    k_coarsen<<<256, 256, 0, s2>>>(adj);
    cudaEventRecord(ev_join, s2);

    // main chain
    k_lists<<<1, 512>>>();
    k_gather<<<dim3(KK, 128), 256>>>(adj);
    k_agg<<<dim3(TILES_MAX, 4), 256>>>(x);
    k_wgemm<<<dim3(TILES_MAX, 4, 2), 256>>>(W);
    k_norm<<<ROWS_MAX / 8, 256>>>();
    k_statsum<<<32, 256>>>();

    // join: final needs g_coarsen
    cudaStreamWaitEvent(0, ev_join, 0);
    k_final<<<KK, 256>>>(out);
}